// round 8
// baseline (speedup 1.0000x reference)
#include <cuda_runtime.h>
#include <cuda_bf16.h>
#include <cstdint>

// Problem constants
#define B_TOT   2048
#define N_TOK   98
#define C_DIM   256
#define H_NUM   8
#define HD      32
#define NW      512
#define M_ROWS  (B_TOT * N_TOK)          // 200704
#define QKV_N   (3 * C_DIM)              // 768

// -------- scratch (static device globals: no runtime allocation) --------
// NOTE: referenced ONLY from device code (host-passed shadow addrs read as
// zeros via ATS on GB300 — the silent R3-R6 bug).
__device__ float g_qkv[(size_t)M_ROWS * QKV_N];   // ~616 MB
__device__ float g_att[(size_t)M_ROWS * C_DIM];   // ~205 MB
__device__ float g_bias[H_NUM * N_TOK * N_TOK];

// ================= helpers =================
__device__ __forceinline__ void mma16816(float* c, const uint32_t* a, const uint32_t* b) {
    asm volatile(
        "mma.sync.aligned.m16n8k16.row.col.f32.bf16.bf16.f32 "
        "{%0,%1,%2,%3}, {%4,%5,%6,%7}, {%8,%9}, {%0,%1,%2,%3};"
        : "+f"(c[0]), "+f"(c[1]), "+f"(c[2]), "+f"(c[3])
        : "r"(a[0]), "r"(a[1]), "r"(a[2]), "r"(a[3]), "r"(b[0]), "r"(b[1]));
}

__device__ __forceinline__ void split2(float x, float y, uint32_t& hi, uint32_t& lo) {
    __nv_bfloat16 hx = __float2bfloat16(x);
    __nv_bfloat16 hy = __float2bfloat16(y);
    __nv_bfloat16 lx = __float2bfloat16(x - __bfloat162float(hx));
    __nv_bfloat16 ly = __float2bfloat16(y - __bfloat162float(hy));
    hi = (uint32_t)__bfloat16_as_ushort(hx) | ((uint32_t)__bfloat16_as_ushort(hy) << 16);
    lo = (uint32_t)__bfloat16_as_ushort(lx) | ((uint32_t)__bfloat16_as_ushort(ly) << 16);
}

__device__ __forceinline__ uint32_t lds32(const char* p) {
    return *reinterpret_cast<const uint32_t*>(p);
}

// ---------------------------------------------------------------
// Kernel 1: gather relative-position bias  -> g_bias[h][n][m]
// ---------------------------------------------------------------
__global__ void gather_bias_kernel(const float* __restrict__ table,
                                   const int* __restrict__ rel) {
    int idx = blockIdx.x * blockDim.x + threadIdx.x;
    const int total = H_NUM * N_TOK * N_TOK;
    if (idx < total) {
        int h  = idx / (N_TOK * N_TOK);
        int nm = idx % (N_TOK * N_TOK);
        g_bias[idx] = table[rel[nm] * H_NUM + h];
    }
}

// ---------------------------------------------------------------
// HMMA bf16x3 split GEMM (unchanged from R7 — proven)
// ---------------------------------------------------------------
#define RB    80          // row bytes (40 halves)
#define REG_B 10240       // region bytes
#define BUF_B 40960       // buffer bytes

__device__ __forceinline__ void ld_chunk(const float* __restrict__ A,
                                         const float* __restrict__ W,
                                         int m0, int n0, int k0, int tid,
                                         float4* r) {
#pragma unroll
    for (int i = 0; i < 4; i++) {
        int f4  = tid + i * 256;
        int row = f4 >> 3;
        int c4  = (f4 & 7) << 2;
        r[i]     = *reinterpret_cast<const float4*>(A + (size_t)(m0 + row) * C_DIM + k0 + c4);
        r[4 + i] = *reinterpret_cast<const float4*>(W + (size_t)(n0 + row) * C_DIM + k0 + c4);
    }
}

__device__ __forceinline__ void st_chunk(char* buf, int tid, const float4* r) {
#pragma unroll
    for (int i = 0; i < 4; i++) {
        int f4  = tid + i * 256;
        int row = f4 >> 3;
        int c4  = (f4 & 7) << 2;
        int off = row * RB + c4 * 2;
        uint32_t h01, l01, h23, l23;
        split2(r[i].x, r[i].y, h01, l01);
        split2(r[i].z, r[i].w, h23, l23);
        *reinterpret_cast<uint2*>(buf + off)         = make_uint2(h01, h23);
        *reinterpret_cast<uint2*>(buf + REG_B + off) = make_uint2(l01, l23);
        split2(r[4 + i].x, r[4 + i].y, h01, l01);
        split2(r[4 + i].z, r[4 + i].w, h23, l23);
        *reinterpret_cast<uint2*>(buf + 2 * REG_B + off) = make_uint2(h01, h23);
        *reinterpret_cast<uint2*>(buf + 3 * REG_B + off) = make_uint2(l01, l23);
    }
}

// m16n8k16 fragment maps (g = lane>>2, t = lane&3)
__device__ __forceinline__ void compute_chunk(const char* sbuf, int wm, int wn,
                                              int lane, float acc[2][8][4]) {
    const int g = lane >> 2;
    const int t = lane & 3;
#pragma unroll
    for (int ks = 0; ks < 32; ks += 16) {
        uint32_t ah[2][4], al[2][4];
#pragma unroll
        for (int mt = 0; mt < 2; mt++) {
            const char* a0p = sbuf + (wm + mt * 16 + g) * RB + (ks + 2 * t) * 2;
            ah[mt][0] = lds32(a0p);
            ah[mt][1] = lds32(a0p + 8 * RB);
            ah[mt][2] = lds32(a0p + 16);
            ah[mt][3] = lds32(a0p + 8 * RB + 16);
            al[mt][0] = lds32(a0p + REG_B);
            al[mt][1] = lds32(a0p + REG_B + 8 * RB);
            al[mt][2] = lds32(a0p + REG_B + 16);
            al[mt][3] = lds32(a0p + REG_B + 8 * RB + 16);
        }
#pragma unroll
        for (int q = 0; q < 8; q++) {
            const char* b0p = sbuf + 2 * REG_B + (wn + q * 8 + g) * RB + (ks + 2 * t) * 2;
            uint32_t bh[2], bl[2];
            bh[0] = lds32(b0p);
            bh[1] = lds32(b0p + 16);
            bl[0] = lds32(b0p + REG_B);
            bl[1] = lds32(b0p + REG_B + 16);
#pragma unroll
            for (int mt = 0; mt < 2; mt++) {
                mma16816(acc[mt][q], ah[mt], bh);
                mma16816(acc[mt][q], ah[mt], bl);
                mma16816(acc[mt][q], al[mt], bh);
            }
        }
    }
}

__device__ __forceinline__ void hgemm_body(char* smem,
                                           const float* __restrict__ A,
                                           const float* __restrict__ W,
                                           const float* __restrict__ bias,
                                           float* __restrict__ C, int Ntot) {
    const int tid  = threadIdx.x;
    const int wid  = tid >> 5;
    const int lane = tid & 31;
    const int m0 = blockIdx.y * 128;
    const int n0 = blockIdx.x * 128;
    const int wm = (wid >> 1) * 32;
    const int wn = (wid & 1) * 64;

    float acc[2][8][4];
#pragma unroll
    for (int mt = 0; mt < 2; mt++)
#pragma unroll
        for (int nt = 0; nt < 8; nt++)
#pragma unroll
            for (int j = 0; j < 4; j++) acc[mt][nt][j] = 0.f;

    float4 pref[8];
    ld_chunk(A, W, m0, n0, 0, tid, pref);
    st_chunk(smem, tid, pref);
    __syncthreads();

#pragma unroll 1
    for (int ch = 0; ch < 8; ch++) {
        if (ch < 7) ld_chunk(A, W, m0, n0, (ch + 1) * 32, tid, pref);
        compute_chunk(smem + (ch & 1) * BUF_B, wm, wn, lane, acc);
        if (ch < 7) st_chunk(smem + ((ch + 1) & 1) * BUF_B, tid, pref);
        __syncthreads();
    }

    const int g = lane >> 2;
    const int t = lane & 3;
#pragma unroll
    for (int mt = 0; mt < 2; mt++) {
#pragma unroll
        for (int q = 0; q < 8; q++) {
            int rr = m0 + wm + mt * 16 + g;
            int cc = n0 + wn + q * 8 + 2 * t;
            float b0 = bias[cc], b1 = bias[cc + 1];
            float2 v0 = make_float2(acc[mt][q][0] + b0, acc[mt][q][1] + b1);
            float2 v1 = make_float2(acc[mt][q][2] + b0, acc[mt][q][3] + b1);
            *reinterpret_cast<float2*>(C + (size_t)rr * Ntot + cc)       = v0;
            *reinterpret_cast<float2*>(C + (size_t)(rr + 8) * Ntot + cc) = v1;
        }
    }
}

__global__ void __launch_bounds__(256, 2)
qkv_gemm_kernel(const float* __restrict__ x, const float* __restrict__ w,
                const float* __restrict__ b) {
    extern __shared__ char smem[];
    hgemm_body(smem, x, w, b, g_qkv, QKV_N);
}

__global__ void __launch_bounds__(256, 2)
proj_gemm_kernel(const float* __restrict__ w, const float* __restrict__ b,
                 float* __restrict__ out) {
    extern __shared__ char smem[];
    hgemm_body(smem, g_att, w, b, out, C_DIM);
}

// ---------------------------------------------------------------
// Kernel 3: HMMA attention, one CTA per (b,h). Pad 98 -> 128.
//   S = q k^T  (bf16x3 mma, RB=80 layout, reuses compute_chunk)
//   S += bias+mask; pad = -1e9 ; softmax (all 128 rows)
//   P split -> bf16 hi/lo ; O = P V via mma with B = V^T
// smem: [P zone 69632 | S 67584 | VT 17408] = 154624 B (q/k tiles
// live in the P zone during phase 1, then get overwritten by P).
// ---------------------------------------------------------------
#define PM    128
#define SP    132                 // S pitch (words)
#define PRB   272                 // P row pitch (bytes)
#define PREG  (PM * PRB)          // 34816
#define VRB   272
#define VREG  (HD * VRB)          // 8704
#define OFF_S   (2 * PREG)        // 69632
#define OFF_VT  (OFF_S + PM * SP * 4)   // 137216
#define ATTN_SMEM (OFF_VT + 2 * VREG)   // 154624

__global__ void __launch_bounds__(256)
attn_hmma_kernel(const float* __restrict__ mask) {
    extern __shared__ char smem[];
    const int tid  = threadIdx.x;
    const int wid  = tid >> 5;
    const int lane = tid & 31;
    const int g = lane >> 2;
    const int t = lane & 3;
    const int bh = blockIdx.x;
    const int b  = bh >> 3;
    const int h  = bh & 7;
    const float scale = 0.17677669529663687f;   // 1/sqrt(32)

    char*  qk = smem;                                   // q hi/lo, k hi/lo (RB=80)
    char*  Pz = smem;                                   // P hi/lo (overlays qk later)
    float* S  = reinterpret_cast<float*>(smem + OFF_S);
    char*  vt = smem + OFF_VT;

    // ---- phase 0: load q,k (split, RB=80 layout) and V^T (split) ----
#pragma unroll
    for (int i = 0; i < 4; i++) {
        int s = tid + 256 * i;          // 1024 slots: 128 rows x 8 quads
        int row = s >> 3;
        int c4  = (s & 7) << 2;
        float4 qv = make_float4(0.f, 0.f, 0.f, 0.f);
        float4 kv = qv;
        if (row < N_TOK) {
            size_t base = ((size_t)(b * N_TOK + row)) * QKV_N + h * HD + c4;
            qv = *reinterpret_cast<const float4*>(g_qkv + base);
            kv = *reinterpret_cast<const float4*>(g_qkv + base + C_DIM);
            qv.x *= scale; qv.y *= scale; qv.z *= scale; qv.w *= scale;
        }
        int off = row * RB + c4 * 2;
        uint32_t h01, l01, h23, l23;
        split2(qv.x, qv.y, h01, l01);
        split2(qv.z, qv.w, h23, l23);
        *reinterpret_cast<uint2*>(qk + off)         = make_uint2(h01, h23);
        *reinterpret_cast<uint2*>(qk + REG_B + off) = make_uint2(l01, l23);
        split2(kv.x, kv.y, h01, l01);
        split2(kv.z, kv.w, h23, l23);
        *reinterpret_cast<uint2*>(qk + 2 * REG_B + off) = make_uint2(h01, h23);
        *reinterpret_cast<uint2*>(qk + 3 * REG_B + off) = make_uint2(l01, l23);
    }
    // V^T: vt[d][token] bf16 hi/lo; token pairs packed in one word
#pragma unroll
    for (int i = 0; i < 2; i++) {
        int s  = tid + 256 * i;          // 512 slots: 64 token-pairs x 8 d-quads
        int tp = s >> 3;
        int d4 = (s & 7) << 2;
        int t0 = 2 * tp, t1 = 2 * tp + 1;
        float4 v0 = make_float4(0.f, 0.f, 0.f, 0.f), v1 = v0;
        if (t0 < N_TOK)
            v0 = *reinterpret_cast<const float4*>(
                g_qkv + ((size_t)(b * N_TOK + t0)) * QKV_N + h * HD + 2 * C_DIM + d4);
        if (t1 < N_TOK)
            v1 = *reinterpret_cast<const float4*>(
                g_qkv + ((size_t)(b * N_TOK + t1)) * QKV_N + h * HD + 2 * C_DIM + d4);
        float e0[4] = { v0.x, v0.y, v0.z, v0.w };
        float e1[4] = { v1.x, v1.y, v1.z, v1.w };
#pragma unroll
        for (int d = 0; d < 4; d++) {
            uint32_t hi, lo;
            split2(e0[d], e1[d], hi, lo);
            *reinterpret_cast<uint32_t*>(vt + (d4 + d) * VRB + tp * 4)        = hi;
            *reinterpret_cast<uint32_t*>(vt + VREG + (d4 + d) * VRB + tp * 4) = lo;
        }
    }
    __syncthreads();

    // ---- phase 1: S = q k^T via mma (single BK=32 chunk) ----
    const int wm = (wid >> 1) * 32;
    const int wn = (wid & 1) * 64;
    float acc[2][8][4];
#pragma unroll
    for (int mt = 0; mt < 2; mt++)
#pragma unroll
        for (int q = 0; q < 8; q++)
#pragma unroll
            for (int j = 0; j < 4; j++) acc[mt][q][j] = 0.f;
    compute_chunk(qk, wm, wn, lane, acc);

    // ---- phase 2: S += bias + mask ; pad = -1e9 ; write smem ----
    {
        const float* bp = g_bias + (size_t)h * (N_TOK * N_TOK);
        const float* mp = mask + (size_t)(b & (NW - 1)) * (N_TOK * N_TOK);
#pragma unroll
        for (int mt = 0; mt < 2; mt++) {
#pragma unroll
            for (int q = 0; q < 8; q++) {
                int rr0 = wm + mt * 16 + g;
                int rr1 = rr0 + 8;
                int cc  = wn + q * 8 + 2 * t;
                bool c0 = (cc < N_TOK), c1 = (cc + 1 < N_TOK);
                float2 o0, o1;
                o0.x = (rr0 < N_TOK && c0) ? acc[mt][q][0] + bp[rr0 * N_TOK + cc]     + mp[rr0 * N_TOK + cc]     : -1e9f;
                o0.y = (rr0 < N_TOK && c1) ? acc[mt][q][1] + bp[rr0 * N_TOK + cc + 1] + mp[rr0 * N_TOK + cc + 1] : -1e9f;
                o1.x = (rr1 < N_TOK && c0) ? acc[mt][q][2] + bp[rr1 * N_TOK + cc]     + mp[rr1 * N_TOK + cc]     : -1e9f;
                o1.y = (rr1 < N_TOK && c1) ? acc[mt][q][3] + bp[rr1 * N_TOK + cc + 1] + mp[rr1 * N_TOK + cc + 1] : -1e9f;
                *reinterpret_cast<float2*>(S + rr0 * SP + cc) = o0;
                *reinterpret_cast<float2*>(S + rr1 * SP + cc) = o1;
            }
        }
    }
    __syncthreads();

    // ---- phase 3: row softmax over all 128 rows / 128 cols ----
    {
        const int ln = tid & 31, wp = tid >> 5;
        for (int i = wp; i < PM; i += 8) {
            float* row = S + i * SP;
            float m = -1e30f;
            for (int j = ln; j < PM; j += 32) m = fmaxf(m, row[j]);
#pragma unroll
            for (int off = 16; off; off >>= 1)
                m = fmaxf(m, __shfl_xor_sync(0xFFFFFFFFu, m, off));
            float sum = 0.f;
            for (int j = ln; j < PM; j += 32) {
                float e = __expf(row[j] - m);
                row[j] = e;
                sum += e;
            }
#pragma unroll
            for (int off = 16; off; off >>= 1)
                sum += __shfl_xor_sync(0xFFFFFFFFu, sum, off);
            float inv = 1.f / sum;
            for (int j = ln; j < PM; j += 32) row[j] *= inv;
        }
    }
    __syncthreads();

    // ---- phase 4: split P -> bf16 hi/lo (overlays q/k zone) ----
#pragma unroll
    for (int i = 0; i < 16; i++) {
        int s   = tid + 256 * i;         // 4096 quads: 128 rows x 32 quads
        int row = s >> 5;
        int c4  = (s & 31) << 2;
        float4 p = *reinterpret_cast<const float4*>(S + row * SP + c4);
        uint32_t h01, l01, h23, l23;
        split2(p.x, p.y, h01, l01);
        split2(p.z, p.w, h23, l23);
        int off = row * PRB + c4 * 2;
        *reinterpret_cast<uint2*>(Pz + off)        = make_uint2(h01, h23);
        *reinterpret_cast<uint2*>(Pz + PREG + off) = make_uint2(l01, l23);
    }
    __syncthreads();

    // ---- phase 5: O = P V via mma (A=P k=128, B=V^T 32xk) ----
    const int wn2 = (wid & 1) * 16;
    float oacc[2][2][4];
#pragma unroll
    for (int mt = 0; mt < 2; mt++)
#pragma unroll
        for (int q = 0; q < 2; q++)
#pragma unroll
            for (int j = 0; j < 4; j++) oacc[mt][q][j] = 0.f;

#pragma unroll
    for (int kc = 0; kc < 8; kc++) {
        const int ks = kc * 16;
        uint32_t ah[2][4], al[2][4];
#pragma unroll
        for (int mt = 0; mt < 2; mt++) {
            const char* a0p = Pz + (wm + mt * 16 + g) * PRB + (ks + 2 * t) * 2;
            ah[mt][0] = lds32(a0p);
            ah[mt][1] = lds32(a0p + 8 * PRB);
            ah[mt][2] = lds32(a0p + 16);
            ah[mt][3] = lds32(a0p + 8 * PRB + 16);
            al[mt][0] = lds32(a0p + PREG);
            al[mt][1] = lds32(a0p + PREG + 8 * PRB);
            al[mt][2] = lds32(a0p + PREG + 16);
            al[mt][3] = lds32(a0p + PREG + 8 * PRB + 16);
        }
#pragma unroll
        for (int q = 0; q < 2; q++) {
            const char* b0p = vt + (wn2 + q * 8 + g) * VRB + (ks + 2 * t) * 2;
            uint32_t bh[2], bl[2];
            bh[0] = lds32(b0p);
            bh[1] = lds32(b0p + 16);
            bl[0] = lds32(b0p + VREG);
            bl[1] = lds32(b0p + VREG + 16);
#pragma unroll
            for (int mt = 0; mt < 2; mt++) {
                mma16816(oacc[mt][q], ah[mt], bh);
                mma16816(oacc[mt][q], ah[mt], bl);
                mma16816(oacc[mt][q], al[mt], bh);
            }
        }
    }

    // ---- phase 6: write O rows < 98 ----
#pragma unroll
    for (int mt = 0; mt < 2; mt++) {
#pragma unroll
        for (int q = 0; q < 2; q++) {
            int rr = wm + mt * 16 + g;
            int cc = h * HD + wn2 + q * 8 + 2 * t;
            if (rr < N_TOK)
                *reinterpret_cast<float2*>(g_att + (size_t)(b * N_TOK + rr) * C_DIM + cc)
                    = make_float2(oacc[mt][q][0], oacc[mt][q][1]);
            if (rr + 8 < N_TOK)
                *reinterpret_cast<float2*>(g_att + (size_t)(b * N_TOK + rr + 8) * C_DIM + cc)
                    = make_float2(oacc[mt][q][2], oacc[mt][q][3]);
        }
    }
}

// ---------------------------------------------------------------
// Launch
// ---------------------------------------------------------------
extern "C" void kernel_launch(void* const* d_in, const int* in_sizes, int n_in,
                              void* d_out, int out_size) {
    const float* x          = (const float*)d_in[0];
    const float* mask       = (const float*)d_in[1];
    const float* qkv_w      = (const float*)d_in[2];
    const float* qkv_b      = (const float*)d_in[3];
    const float* proj_w     = (const float*)d_in[4];
    const float* proj_b     = (const float*)d_in[5];
    const float* bias_table = (const float*)d_in[6];
    const int*   rel_index  = (const int*)d_in[7];
    float* out = (float*)d_out;

    cudaFuncSetAttribute(attn_hmma_kernel,
                         cudaFuncAttributeMaxDynamicSharedMemorySize, ATTN_SMEM);
    const int gemm_smem = 2 * BUF_B;   // 81920
    cudaFuncSetAttribute(qkv_gemm_kernel,
                         cudaFuncAttributeMaxDynamicSharedMemorySize, gemm_smem);
    cudaFuncSetAttribute(proj_gemm_kernel,
                         cudaFuncAttributeMaxDynamicSharedMemorySize, gemm_smem);

    // 1) bias gather
    {
        int total = H_NUM * N_TOK * N_TOK;
        gather_bias_kernel<<<(total + 255) / 256, 256>>>(bias_table, rel_index);
    }
    // 2) QKV projection (HMMA bf16x3): [200704,256] x [768,256]^T -> g_qkv
    {
        dim3 grid(QKV_N / 128, M_ROWS / 128);
        qkv_gemm_kernel<<<grid, 256, gemm_smem>>>(x, qkv_w, qkv_b);
    }
    // 3) HMMA attention per (b,h)
    {
        attn_hmma_kernel<<<B_TOT * H_NUM, 256, ATTN_SMEM>>>(mask);
    }
    // 4) output projection (HMMA bf16x3): [200704,256] x [256,256]^T -> d_out
    {
        dim3 grid(C_DIM / 128, M_ROWS / 128);
        proj_gemm_kernel<<<grid, 256, gemm_smem>>>(proj_w, proj_b, out);
    }
}

// round 9
// speedup vs baseline: 1.8414x; 1.8414x over previous
#include <cuda_runtime.h>
#include <cuda_bf16.h>
#include <cstdint>

// Problem constants
#define B_TOT   2048
#define N_TOK   98
#define C_DIM   256
#define H_NUM   8
#define HD      32
#define NW      512
#define M_ROWS  (B_TOT * N_TOK)          // 200704
#define QKV_N   (3 * C_DIM)              // 768

// -------- scratch (static device globals: no runtime allocation) --------
// NOTE: referenced ONLY from device code (host-passed shadow addrs read as
// zeros via ATS on GB300 — the silent R3-R6 bug).
__device__ float g_qkv[(size_t)M_ROWS * QKV_N];   // ~616 MB
__device__ float g_att[(size_t)M_ROWS * C_DIM];   // ~205 MB
__device__ float g_bias[H_NUM * N_TOK * N_TOK];

// ================= helpers =================
__device__ __forceinline__ void mma16816(float* c, const uint32_t* a, const uint32_t* b) {
    asm volatile(
        "mma.sync.aligned.m16n8k16.row.col.f32.bf16.bf16.f32 "
        "{%0,%1,%2,%3}, {%4,%5,%6,%7}, {%8,%9}, {%0,%1,%2,%3};"
        : "+f"(c[0]), "+f"(c[1]), "+f"(c[2]), "+f"(c[3])
        : "r"(a[0]), "r"(a[1]), "r"(a[2]), "r"(a[3]), "r"(b[0]), "r"(b[1]));
}

__device__ __forceinline__ void split2(float x, float y, uint32_t& hi, uint32_t& lo) {
    __nv_bfloat16 hx = __float2bfloat16(x);
    __nv_bfloat16 hy = __float2bfloat16(y);
    __nv_bfloat16 lx = __float2bfloat16(x - __bfloat162float(hx));
    __nv_bfloat16 ly = __float2bfloat16(y - __bfloat162float(hy));
    hi = (uint32_t)__bfloat16_as_ushort(hx) | ((uint32_t)__bfloat16_as_ushort(hy) << 16);
    lo = (uint32_t)__bfloat16_as_ushort(lx) | ((uint32_t)__bfloat16_as_ushort(ly) << 16);
}

__device__ __forceinline__ uint32_t lds32(const char* p) {
    return *reinterpret_cast<const uint32_t*>(p);
}

// ---------------------------------------------------------------
// Kernel 1: gather relative-position bias  -> g_bias[h][n][m]
// ---------------------------------------------------------------
__global__ void gather_bias_kernel(const float* __restrict__ table,
                                   const int* __restrict__ rel) {
    int idx = blockIdx.x * blockDim.x + threadIdx.x;
    const int total = H_NUM * N_TOK * N_TOK;
    if (idx < total) {
        int h  = idx / (N_TOK * N_TOK);
        int nm = idx % (N_TOK * N_TOK);
        g_bias[idx] = table[rel[nm] * H_NUM + h];
    }
}

// ---------------------------------------------------------------
// HMMA bf16x3 split GEMM (unchanged — proven in R7)
// ---------------------------------------------------------------
#define RB    80          // row bytes (40 halves)
#define REG_B 10240       // region bytes
#define BUF_B 40960       // buffer bytes

__device__ __forceinline__ void ld_chunk(const float* __restrict__ A,
                                         const float* __restrict__ W,
                                         int m0, int n0, int k0, int tid,
                                         float4* r) {
#pragma unroll
    for (int i = 0; i < 4; i++) {
        int f4  = tid + i * 256;
        int row = f4 >> 3;
        int c4  = (f4 & 7) << 2;
        r[i]     = *reinterpret_cast<const float4*>(A + (size_t)(m0 + row) * C_DIM + k0 + c4);
        r[4 + i] = *reinterpret_cast<const float4*>(W + (size_t)(n0 + row) * C_DIM + k0 + c4);
    }
}

__device__ __forceinline__ void st_chunk(char* buf, int tid, const float4* r) {
#pragma unroll
    for (int i = 0; i < 4; i++) {
        int f4  = tid + i * 256;
        int row = f4 >> 3;
        int c4  = (f4 & 7) << 2;
        int off = row * RB + c4 * 2;
        uint32_t h01, l01, h23, l23;
        split2(r[i].x, r[i].y, h01, l01);
        split2(r[i].z, r[i].w, h23, l23);
        *reinterpret_cast<uint2*>(buf + off)         = make_uint2(h01, h23);
        *reinterpret_cast<uint2*>(buf + REG_B + off) = make_uint2(l01, l23);
        split2(r[4 + i].x, r[4 + i].y, h01, l01);
        split2(r[4 + i].z, r[4 + i].w, h23, l23);
        *reinterpret_cast<uint2*>(buf + 2 * REG_B + off) = make_uint2(h01, h23);
        *reinterpret_cast<uint2*>(buf + 3 * REG_B + off) = make_uint2(l01, l23);
    }
}

// m16n8k16 fragment maps (g = lane>>2, t = lane&3)
__device__ __forceinline__ void compute_chunk(const char* sbuf, int wm, int wn,
                                              int lane, float acc[2][8][4]) {
    const int g = lane >> 2;
    const int t = lane & 3;
#pragma unroll
    for (int ks = 0; ks < 32; ks += 16) {
        uint32_t ah[2][4], al[2][4];
#pragma unroll
        for (int mt = 0; mt < 2; mt++) {
            const char* a0p = sbuf + (wm + mt * 16 + g) * RB + (ks + 2 * t) * 2;
            ah[mt][0] = lds32(a0p);
            ah[mt][1] = lds32(a0p + 8 * RB);
            ah[mt][2] = lds32(a0p + 16);
            ah[mt][3] = lds32(a0p + 8 * RB + 16);
            al[mt][0] = lds32(a0p + REG_B);
            al[mt][1] = lds32(a0p + REG_B + 8 * RB);
            al[mt][2] = lds32(a0p + REG_B + 16);
            al[mt][3] = lds32(a0p + REG_B + 8 * RB + 16);
        }
#pragma unroll
        for (int q = 0; q < 8; q++) {
            const char* b0p = sbuf + 2 * REG_B + (wn + q * 8 + g) * RB + (ks + 2 * t) * 2;
            uint32_t bh[2], bl[2];
            bh[0] = lds32(b0p);
            bh[1] = lds32(b0p + 16);
            bl[0] = lds32(b0p + REG_B);
            bl[1] = lds32(b0p + REG_B + 16);
#pragma unroll
            for (int mt = 0; mt < 2; mt++) {
                mma16816(acc[mt][q], ah[mt], bh);
                mma16816(acc[mt][q], ah[mt], bl);
                mma16816(acc[mt][q], al[mt], bh);
            }
        }
    }
}

__device__ __forceinline__ void hgemm_body(char* smem,
                                           const float* __restrict__ A,
                                           const float* __restrict__ W,
                                           const float* __restrict__ bias,
                                           float* __restrict__ C, int Ntot) {
    const int tid  = threadIdx.x;
    const int wid  = tid >> 5;
    const int lane = tid & 31;
    const int m0 = blockIdx.y * 128;
    const int n0 = blockIdx.x * 128;
    const int wm = (wid >> 1) * 32;
    const int wn = (wid & 1) * 64;

    float acc[2][8][4];
#pragma unroll
    for (int mt = 0; mt < 2; mt++)
#pragma unroll
        for (int nt = 0; nt < 8; nt++)
#pragma unroll
            for (int j = 0; j < 4; j++) acc[mt][nt][j] = 0.f;

    float4 pref[8];
    ld_chunk(A, W, m0, n0, 0, tid, pref);
    st_chunk(smem, tid, pref);
    __syncthreads();

#pragma unroll 1
    for (int ch = 0; ch < 8; ch++) {
        if (ch < 7) ld_chunk(A, W, m0, n0, (ch + 1) * 32, tid, pref);
        compute_chunk(smem + (ch & 1) * BUF_B, wm, wn, lane, acc);
        if (ch < 7) st_chunk(smem + ((ch + 1) & 1) * BUF_B, tid, pref);
        __syncthreads();
    }

    const int g = lane >> 2;
    const int t = lane & 3;
#pragma unroll
    for (int mt = 0; mt < 2; mt++) {
#pragma unroll
        for (int q = 0; q < 8; q++) {
            int rr = m0 + wm + mt * 16 + g;
            int cc = n0 + wn + q * 8 + 2 * t;
            float b0 = bias[cc], b1 = bias[cc + 1];
            float2 v0 = make_float2(acc[mt][q][0] + b0, acc[mt][q][1] + b1);
            float2 v1 = make_float2(acc[mt][q][2] + b0, acc[mt][q][3] + b1);
            *reinterpret_cast<float2*>(C + (size_t)rr * Ntot + cc)       = v0;
            *reinterpret_cast<float2*>(C + (size_t)(rr + 8) * Ntot + cc) = v1;
        }
    }
}

__global__ void __launch_bounds__(256, 2)
qkv_gemm_kernel(const float* __restrict__ x, const float* __restrict__ w,
                const float* __restrict__ b) {
    extern __shared__ char smem[];
    hgemm_body(smem, x, w, b, g_qkv, QKV_N);
}

__global__ void __launch_bounds__(256, 2)
proj_gemm_kernel(const float* __restrict__ w, const float* __restrict__ b,
                 float* __restrict__ out) {
    extern __shared__ char smem[];
    hgemm_body(smem, g_att, w, b, out, C_DIM);
}

// ---------------------------------------------------------------
// Kernel 3: HMMA attention with REGISTER softmax. One CTA per (b,h).
// smem: [Pz 69632 (q/k tiles live here in phase 1) | VT 17408 | red 2048]
//   = 89088 B -> 2 CTAs/SM.
// ---------------------------------------------------------------
#define PM    128
#define PRB   272                 // P row pitch (bytes)
#define PREG  (PM * PRB)          // 34816
#define VRB   272
#define VREG  (HD * VRB)          // 8704
#define OFF_VT   (2 * PREG)             // 69632
#define OFF_RED  (OFF_VT + 2 * VREG)    // 87040
#define ATTN_SMEM (OFF_RED + 2048)      // 89088

__global__ void __launch_bounds__(256, 2)
attn_hmma_kernel(const float* __restrict__ mask) {
    extern __shared__ char smem[];
    const int tid  = threadIdx.x;
    const int wid  = tid >> 5;
    const int lane = tid & 31;
    const int g = lane >> 2;
    const int t = lane & 3;
    const int bh = blockIdx.x;
    const int b  = bh >> 3;
    const int h  = bh & 7;
    const float scale = 0.17677669529663687f;   // 1/sqrt(32)

    char*  qk = smem;                    // q hi/lo, k hi/lo (RB=80), phase 1 only
    char*  Pz = smem;                    // P hi/lo (overlays qk after sync)
    char*  vt = smem + OFF_VT;
    float* redM = reinterpret_cast<float*>(smem + OFF_RED);        // [2][128]
    float* redS = redM + 256;                                      // [2][128]

    // ---- phase 0: load q,k (split, RB=80 layout) and V^T (split) ----
#pragma unroll
    for (int i = 0; i < 4; i++) {
        int s = tid + 256 * i;          // 1024 slots: 128 rows x 8 quads
        int row = s >> 3;
        int c4  = (s & 7) << 2;
        float4 qv = make_float4(0.f, 0.f, 0.f, 0.f);
        float4 kv = qv;
        if (row < N_TOK) {
            size_t base = ((size_t)(b * N_TOK + row)) * QKV_N + h * HD + c4;
            qv = *reinterpret_cast<const float4*>(g_qkv + base);
            kv = *reinterpret_cast<const float4*>(g_qkv + base + C_DIM);
            qv.x *= scale; qv.y *= scale; qv.z *= scale; qv.w *= scale;
        }
        int off = row * RB + c4 * 2;
        uint32_t h01, l01, h23, l23;
        split2(qv.x, qv.y, h01, l01);
        split2(qv.z, qv.w, h23, l23);
        *reinterpret_cast<uint2*>(qk + off)         = make_uint2(h01, h23);
        *reinterpret_cast<uint2*>(qk + REG_B + off) = make_uint2(l01, l23);
        split2(kv.x, kv.y, h01, l01);
        split2(kv.z, kv.w, h23, l23);
        *reinterpret_cast<uint2*>(qk + 2 * REG_B + off) = make_uint2(h01, h23);
        *reinterpret_cast<uint2*>(qk + 3 * REG_B + off) = make_uint2(l01, l23);
    }
    // V^T: vt[d][token-pair] bf16 hi/lo
#pragma unroll
    for (int i = 0; i < 2; i++) {
        int s  = tid + 256 * i;          // 512 slots: 64 token-pairs x 8 d-quads
        int tp = s >> 3;
        int d4 = (s & 7) << 2;
        int t0 = 2 * tp, t1 = 2 * tp + 1;
        float4 v0 = make_float4(0.f, 0.f, 0.f, 0.f), v1 = v0;
        if (t0 < N_TOK)
            v0 = *reinterpret_cast<const float4*>(
                g_qkv + ((size_t)(b * N_TOK + t0)) * QKV_N + h * HD + 2 * C_DIM + d4);
        if (t1 < N_TOK)
            v1 = *reinterpret_cast<const float4*>(
                g_qkv + ((size_t)(b * N_TOK + t1)) * QKV_N + h * HD + 2 * C_DIM + d4);
        float e0[4] = { v0.x, v0.y, v0.z, v0.w };
        float e1[4] = { v1.x, v1.y, v1.z, v1.w };
#pragma unroll
        for (int d = 0; d < 4; d++) {
            uint32_t hi, lo;
            split2(e0[d], e1[d], hi, lo);
            *reinterpret_cast<uint32_t*>(vt + (d4 + d) * VRB + tp * 4)        = hi;
            *reinterpret_cast<uint32_t*>(vt + VREG + (d4 + d) * VRB + tp * 4) = lo;
        }
    }
    __syncthreads();

    // ---- phase 1: S = q k^T via mma ----
    const int wm = (wid >> 1) * 32;
    const int wn = (wid & 1) * 64;
    const int wpair = wid & 1;
    float acc[2][8][4];
#pragma unroll
    for (int mt = 0; mt < 2; mt++)
#pragma unroll
        for (int q = 0; q < 8; q++)
#pragma unroll
            for (int j = 0; j < 4; j++) acc[mt][q][j] = 0.f;
    compute_chunk(qk, wm, wn, lane, acc);

    // ---- phase 2: add bias+mask in registers; pad = -1e9 ----
    {
        const float* bp = g_bias + (size_t)h * (N_TOK * N_TOK);
        const float* mp = mask + (size_t)(b & (NW - 1)) * (N_TOK * N_TOK);
#pragma unroll
        for (int mt = 0; mt < 2; mt++) {
            int rr0 = wm + mt * 16 + g;
            int rr1 = rr0 + 8;
#pragma unroll
            for (int q = 0; q < 8; q++) {
                int cc = wn + q * 8 + 2 * t;
                bool c0 = (cc < N_TOK), c1 = (cc + 1 < N_TOK);
                acc[mt][q][0] = (rr0 < N_TOK && c0) ? acc[mt][q][0] + bp[rr0 * N_TOK + cc]     + mp[rr0 * N_TOK + cc]     : -1e9f;
                acc[mt][q][1] = (rr0 < N_TOK && c1) ? acc[mt][q][1] + bp[rr0 * N_TOK + cc + 1] + mp[rr0 * N_TOK + cc + 1] : -1e9f;
                acc[mt][q][2] = (rr1 < N_TOK && c0) ? acc[mt][q][2] + bp[rr1 * N_TOK + cc]     + mp[rr1 * N_TOK + cc]     : -1e9f;
                acc[mt][q][3] = (rr1 < N_TOK && c1) ? acc[mt][q][3] + bp[rr1 * N_TOK + cc + 1] + mp[rr1 * N_TOK + cc + 1] : -1e9f;
            }
        }
    }

    // ---- phase 3: register softmax ----
    // 3a: per-row max (this warp's half: 16 values per lane -> t-group shfl)
#pragma unroll
    for (int mt = 0; mt < 2; mt++) {
        float m0 = -1e30f, m1 = -1e30f;
#pragma unroll
        for (int q = 0; q < 8; q++) {
            m0 = fmaxf(m0, fmaxf(acc[mt][q][0], acc[mt][q][1]));
            m1 = fmaxf(m1, fmaxf(acc[mt][q][2], acc[mt][q][3]));
        }
#pragma unroll
        for (int off = 1; off <= 2; off <<= 1) {
            m0 = fmaxf(m0, __shfl_xor_sync(0xFFFFFFFFu, m0, off));
            m1 = fmaxf(m1, __shfl_xor_sync(0xFFFFFFFFu, m1, off));
        }
        if (t == 0) {
            redM[wpair * PM + wm + mt * 16 + g]     = m0;
            redM[wpair * PM + wm + mt * 16 + g + 8] = m1;
        }
    }
    __syncthreads();

    // 3b: exp + per-row sum
#pragma unroll
    for (int mt = 0; mt < 2; mt++) {
        int r0 = wm + mt * 16 + g;
        float M0 = fmaxf(redM[r0], redM[PM + r0]);
        float M1 = fmaxf(redM[r0 + 8], redM[PM + r0 + 8]);
        float s0 = 0.f, s1 = 0.f;
#pragma unroll
        for (int q = 0; q < 8; q++) {
            float e0 = __expf(acc[mt][q][0] - M0);
            float e1 = __expf(acc[mt][q][1] - M0);
            float e2 = __expf(acc[mt][q][2] - M1);
            float e3 = __expf(acc[mt][q][3] - M1);
            acc[mt][q][0] = e0; acc[mt][q][1] = e1;
            acc[mt][q][2] = e2; acc[mt][q][3] = e3;
            s0 += e0 + e1;
            s1 += e2 + e3;
        }
#pragma unroll
        for (int off = 1; off <= 2; off <<= 1) {
            s0 += __shfl_xor_sync(0xFFFFFFFFu, s0, off);
            s1 += __shfl_xor_sync(0xFFFFFFFFu, s1, off);
        }
        if (t == 0) {
            redS[wpair * PM + r0]     = s0;
            redS[wpair * PM + r0 + 8] = s1;
        }
    }
    __syncthreads();   // also fences qk reads (done) vs Pz writes below

    // 3c: normalize + write P split bf16 hi/lo directly into Pz
#pragma unroll
    for (int mt = 0; mt < 2; mt++) {
        int r0 = wm + mt * 16 + g;
        float inv0 = 1.f / (redS[r0] + redS[PM + r0]);
        float inv1 = 1.f / (redS[r0 + 8] + redS[PM + r0 + 8]);
#pragma unroll
        for (int q = 0; q < 8; q++) {
            int cc = wn + q * 8 + 2 * t;
            uint32_t hi, lo;
            split2(acc[mt][q][0] * inv0, acc[mt][q][1] * inv0, hi, lo);
            *reinterpret_cast<uint32_t*>(Pz + r0 * PRB + cc * 2)        = hi;
            *reinterpret_cast<uint32_t*>(Pz + PREG + r0 * PRB + cc * 2) = lo;
            split2(acc[mt][q][2] * inv1, acc[mt][q][3] * inv1, hi, lo);
            *reinterpret_cast<uint32_t*>(Pz + (r0 + 8) * PRB + cc * 2)        = hi;
            *reinterpret_cast<uint32_t*>(Pz + PREG + (r0 + 8) * PRB + cc * 2) = lo;
        }
    }
    __syncthreads();

    // ---- phase 4: O = P V via mma (A=P k=128, B=V^T) ----
    const int wn2 = (wid & 1) * 16;
    float oacc[2][2][4];
#pragma unroll
    for (int mt = 0; mt < 2; mt++)
#pragma unroll
        for (int q = 0; q < 2; q++)
#pragma unroll
            for (int j = 0; j < 4; j++) oacc[mt][q][j] = 0.f;

#pragma unroll
    for (int kc = 0; kc < 8; kc++) {
        const int ks = kc * 16;
        uint32_t ah[2][4], al[2][4];
#pragma unroll
        for (int mt = 0; mt < 2; mt++) {
            const char* a0p = Pz + (wm + mt * 16 + g) * PRB + (ks + 2 * t) * 2;
            ah[mt][0] = lds32(a0p);
            ah[mt][1] = lds32(a0p + 8 * PRB);
            ah[mt][2] = lds32(a0p + 16);
            ah[mt][3] = lds32(a0p + 8 * PRB + 16);
            al[mt][0] = lds32(a0p + PREG);
            al[mt][1] = lds32(a0p + PREG + 8 * PRB);
            al[mt][2] = lds32(a0p + PREG + 16);
            al[mt][3] = lds32(a0p + PREG + 8 * PRB + 16);
        }
#pragma unroll
        for (int q = 0; q < 2; q++) {
            const char* b0p = vt + (wn2 + q * 8 + g) * VRB + (ks + 2 * t) * 2;
            uint32_t bh[2], bl[2];
            bh[0] = lds32(b0p);
            bh[1] = lds32(b0p + 16);
            bl[0] = lds32(b0p + VREG);
            bl[1] = lds32(b0p + VREG + 16);
#pragma unroll
            for (int mt = 0; mt < 2; mt++) {
                mma16816(oacc[mt][q], ah[mt], bh);
                mma16816(oacc[mt][q], ah[mt], bl);
                mma16816(oacc[mt][q], al[mt], bh);
            }
        }
    }

    // ---- phase 5: write O rows < 98 ----
#pragma unroll
    for (int mt = 0; mt < 2; mt++) {
#pragma unroll
        for (int q = 0; q < 2; q++) {
            int rr = wm + mt * 16 + g;
            int cc = h * HD + wn2 + q * 8 + 2 * t;
            if (rr < N_TOK)
                *reinterpret_cast<float2*>(g_att + (size_t)(b * N_TOK + rr) * C_DIM + cc)
                    = make_float2(oacc[mt][q][0], oacc[mt][q][1]);
            if (rr + 8 < N_TOK)
                *reinterpret_cast<float2*>(g_att + (size_t)(b * N_TOK + rr + 8) * C_DIM + cc)
                    = make_float2(oacc[mt][q][2], oacc[mt][q][3]);
        }
    }
}

// ---------------------------------------------------------------
// Launch
// ---------------------------------------------------------------
extern "C" void kernel_launch(void* const* d_in, const int* in_sizes, int n_in,
                              void* d_out, int out_size) {
    const float* x          = (const float*)d_in[0];
    const float* mask       = (const float*)d_in[1];
    const float* qkv_w      = (const float*)d_in[2];
    const float* qkv_b      = (const float*)d_in[3];
    const float* proj_w     = (const float*)d_in[4];
    const float* proj_b     = (const float*)d_in[5];
    const float* bias_table = (const float*)d_in[6];
    const int*   rel_index  = (const int*)d_in[7];
    float* out = (float*)d_out;

    cudaFuncSetAttribute(attn_hmma_kernel,
                         cudaFuncAttributeMaxDynamicSharedMemorySize, ATTN_SMEM);
    const int gemm_smem = 2 * BUF_B;   // 81920
    cudaFuncSetAttribute(qkv_gemm_kernel,
                         cudaFuncAttributeMaxDynamicSharedMemorySize, gemm_smem);
    cudaFuncSetAttribute(proj_gemm_kernel,
                         cudaFuncAttributeMaxDynamicSharedMemorySize, gemm_smem);

    // 1) bias gather
    {
        int total = H_NUM * N_TOK * N_TOK;
        gather_bias_kernel<<<(total + 255) / 256, 256>>>(bias_table, rel_index);
    }
    // 2) QKV projection (HMMA bf16x3): [200704,256] x [768,256]^T -> g_qkv
    {
        dim3 grid(QKV_N / 128, M_ROWS / 128);
        qkv_gemm_kernel<<<grid, 256, gemm_smem>>>(x, qkv_w, qkv_b);
    }
    // 3) HMMA attention per (b,h), register softmax
    {
        attn_hmma_kernel<<<B_TOT * H_NUM, 256, ATTN_SMEM>>>(mask);
    }
    // 4) output projection (HMMA bf16x3): [200704,256] x [256,256]^T -> d_out
    {
        dim3 grid(C_DIM / 128, M_ROWS / 128);
        proj_gemm_kernel<<<grid, 256, gemm_smem>>>(proj_w, proj_b, out);
    }
}

// round 10
// speedup vs baseline: 2.1229x; 1.1529x over previous
#include <cuda_runtime.h>
#include <cuda_bf16.h>
#include <cstdint>

// Problem constants
#define B_TOT   2048
#define N_TOK   98
#define C_DIM   256
#define H_NUM   8
#define HD      32
#define NW      512
#define M_ROWS  (B_TOT * N_TOK)          // 200704
#define QKV_N   (3 * C_DIM)              // 768

// -------- scratch (static device globals: no runtime allocation) --------
// NOTE: referenced ONLY from device code (host-passed shadow addrs read as
// zeros via ATS on GB300 — the silent R3-R6 bug).
__device__ float g_qkv[(size_t)M_ROWS * QKV_N];   // ~616 MB
__device__ float g_att[(size_t)M_ROWS * C_DIM];   // ~205 MB
__device__ float g_bias[H_NUM * N_TOK * N_TOK];

// ================= helpers =================
__device__ __forceinline__ uint32_t smem_u32(const void* p) {
    uint32_t a;
    asm("{ .reg .u64 t; cvta.to.shared.u64 t, %1; cvt.u32.u64 %0, t; }"
        : "=r"(a) : "l"(p));
    return a;
}

__device__ __forceinline__ void mma16816(float* c, const uint32_t* a, const uint32_t* b) {
    asm volatile(
        "mma.sync.aligned.m16n8k16.row.col.f32.bf16.bf16.f32 "
        "{%0,%1,%2,%3}, {%4,%5,%6,%7}, {%8,%9}, {%0,%1,%2,%3};"
        : "+f"(c[0]), "+f"(c[1]), "+f"(c[2]), "+f"(c[3])
        : "r"(a[0]), "r"(a[1]), "r"(a[2]), "r"(a[3]), "r"(b[0]), "r"(b[1]));
}

__device__ __forceinline__ void ldsm4(uint32_t* r, uint32_t addr) {
    asm volatile("ldmatrix.sync.aligned.m8n8.x4.shared.b16 {%0,%1,%2,%3}, [%4];"
                 : "=r"(r[0]), "=r"(r[1]), "=r"(r[2]), "=r"(r[3]) : "r"(addr));
}

__device__ __forceinline__ void split2(float x, float y, uint32_t& hi, uint32_t& lo) {
    __nv_bfloat16 hx = __float2bfloat16(x);
    __nv_bfloat16 hy = __float2bfloat16(y);
    __nv_bfloat16 lx = __float2bfloat16(x - __bfloat162float(hx));
    __nv_bfloat16 ly = __float2bfloat16(y - __bfloat162float(hy));
    hi = (uint32_t)__bfloat16_as_ushort(hx) | ((uint32_t)__bfloat16_as_ushort(hy) << 16);
    lo = (uint32_t)__bfloat16_as_ushort(lx) | ((uint32_t)__bfloat16_as_ushort(ly) << 16);
}

// ---------------------------------------------------------------
// Kernel 1: gather relative-position bias  -> g_bias[h][n][m]
// ---------------------------------------------------------------
__global__ void gather_bias_kernel(const float* __restrict__ table,
                                   const int* __restrict__ rel) {
    int idx = blockIdx.x * blockDim.x + threadIdx.x;
    const int total = H_NUM * N_TOK * N_TOK;
    if (idx < total) {
        int h  = idx / (N_TOK * N_TOK);
        int nm = idx % (N_TOK * N_TOK);
        g_bias[idx] = table[rel[nm] * H_NUM + h];
    }
}

// ---------------------------------------------------------------
// HMMA bf16x3 split GEMM, ldmatrix fragment loads.
// CTA: 128x128 tile, BK=32, 8 warps (4x2) of 32x64.
// smem per buffer: A_hi, A_lo, B_hi, B_lo; 128 rows x 32 bf16,
// rows padded to 80 B; double buffered.
// ---------------------------------------------------------------
#define RB    80          // row bytes (40 halves)
#define REG_B 10240       // region bytes
#define BUF_B 40960       // buffer bytes

__device__ __forceinline__ void ld_chunk(const float* __restrict__ A,
                                         const float* __restrict__ W,
                                         int m0, int n0, int k0, int tid,
                                         float4* r) {
#pragma unroll
    for (int i = 0; i < 4; i++) {
        int f4  = tid + i * 256;
        int row = f4 >> 3;
        int c4  = (f4 & 7) << 2;
        r[i]     = *reinterpret_cast<const float4*>(A + (size_t)(m0 + row) * C_DIM + k0 + c4);
        r[4 + i] = *reinterpret_cast<const float4*>(W + (size_t)(n0 + row) * C_DIM + k0 + c4);
    }
}

__device__ __forceinline__ void st_chunk(char* buf, int tid, const float4* r) {
#pragma unroll
    for (int i = 0; i < 4; i++) {
        int f4  = tid + i * 256;
        int row = f4 >> 3;
        int c4  = (f4 & 7) << 2;
        int off = row * RB + c4 * 2;
        uint32_t h01, l01, h23, l23;
        split2(r[i].x, r[i].y, h01, l01);
        split2(r[i].z, r[i].w, h23, l23);
        *reinterpret_cast<uint2*>(buf + off)         = make_uint2(h01, h23);
        *reinterpret_cast<uint2*>(buf + REG_B + off) = make_uint2(l01, l23);
        split2(r[4 + i].x, r[4 + i].y, h01, l01);
        split2(r[4 + i].z, r[4 + i].w, h23, l23);
        *reinterpret_cast<uint2*>(buf + 2 * REG_B + off) = make_uint2(h01, h23);
        *reinterpret_cast<uint2*>(buf + 3 * REG_B + off) = make_uint2(l01, l23);
    }
}

// ldmatrix-based chunk: A region at sbuf+0/REG_B, B region at +2REG_B/+3REG_B.
// A x4: row = base + (lane&15), col += (lane>>4)*8  -> r0..r3 = a0..a3
// B x4 (covers q-pair): row = base + (lane&7) + ((lane>>3)&2)*4,
//                       col += ((lane>>3)&1)*8 -> {bq0[0],bq0[1],bq1[0],bq1[1]}
__device__ __forceinline__ void compute_chunk(uint32_t sbuf, int wm, int wn,
                                              int lane, float acc[2][8][4]) {
    const int arow  = lane & 15;
    const int acol2 = ((lane >> 4) << 3) * 2;
    const int brow  = (lane & 7) + ((lane >> 3) & 2) * 4;
    const int bcol2 = (((lane >> 3) & 1) << 3) * 2;
#pragma unroll
    for (int ks = 0; ks < 32; ks += 16) {
        uint32_t ah[2][4], al[2][4];
#pragma unroll
        for (int mt = 0; mt < 2; mt++) {
            uint32_t aaddr = sbuf + (wm + mt * 16 + arow) * RB + ks * 2 + acol2;
            ldsm4(ah[mt], aaddr);
            ldsm4(al[mt], aaddr + REG_B);
        }
#pragma unroll
        for (int qp = 0; qp < 4; qp++) {
            uint32_t baddr = sbuf + 2 * REG_B + (wn + qp * 16 + brow) * RB + ks * 2 + bcol2;
            uint32_t bh[4], bl[4];
            ldsm4(bh, baddr);
            ldsm4(bl, baddr + REG_B);
#pragma unroll
            for (int hf = 0; hf < 2; hf++) {
                int q = qp * 2 + hf;
#pragma unroll
                for (int mt = 0; mt < 2; mt++) {
                    mma16816(acc[mt][q], ah[mt], bh + 2 * hf);
                    mma16816(acc[mt][q], ah[mt], bl + 2 * hf);
                    mma16816(acc[mt][q], al[mt], bh + 2 * hf);
                }
            }
        }
    }
}

__device__ __forceinline__ void hgemm_body(char* smem,
                                           const float* __restrict__ A,
                                           const float* __restrict__ W,
                                           const float* __restrict__ bias,
                                           float* __restrict__ C, int Ntot) {
    const int tid  = threadIdx.x;
    const int wid  = tid >> 5;
    const int lane = tid & 31;
    const int m0 = blockIdx.y * 128;
    const int n0 = blockIdx.x * 128;
    const int wm = (wid >> 1) * 32;
    const int wn = (wid & 1) * 64;
    const uint32_t sb = smem_u32(smem);

    float acc[2][8][4];
#pragma unroll
    for (int mt = 0; mt < 2; mt++)
#pragma unroll
        for (int nt = 0; nt < 8; nt++)
#pragma unroll
            for (int j = 0; j < 4; j++) acc[mt][nt][j] = 0.f;

    float4 pref[8];
    ld_chunk(A, W, m0, n0, 0, tid, pref);
    st_chunk(smem, tid, pref);
    __syncthreads();

#pragma unroll 1
    for (int ch = 0; ch < 8; ch++) {
        if (ch < 7) ld_chunk(A, W, m0, n0, (ch + 1) * 32, tid, pref);
        compute_chunk(sb + (ch & 1) * BUF_B, wm, wn, lane, acc);
        if (ch < 7) st_chunk(smem + ((ch + 1) & 1) * BUF_B, tid, pref);
        __syncthreads();
    }

    const int g = lane >> 2;
    const int t = lane & 3;
#pragma unroll
    for (int mt = 0; mt < 2; mt++) {
#pragma unroll
        for (int q = 0; q < 8; q++) {
            int rr = m0 + wm + mt * 16 + g;
            int cc = n0 + wn + q * 8 + 2 * t;
            float b0 = bias[cc], b1 = bias[cc + 1];
            float2 v0 = make_float2(acc[mt][q][0] + b0, acc[mt][q][1] + b1);
            float2 v1 = make_float2(acc[mt][q][2] + b0, acc[mt][q][3] + b1);
            *reinterpret_cast<float2*>(C + (size_t)rr * Ntot + cc)       = v0;
            *reinterpret_cast<float2*>(C + (size_t)(rr + 8) * Ntot + cc) = v1;
        }
    }
}

__global__ void __launch_bounds__(256, 2)
qkv_gemm_kernel(const float* __restrict__ x, const float* __restrict__ w,
                const float* __restrict__ b) {
    extern __shared__ char smem[];
    hgemm_body(smem, x, w, b, g_qkv, QKV_N);
}

__global__ void __launch_bounds__(256, 2)
proj_gemm_kernel(const float* __restrict__ w, const float* __restrict__ b,
                 float* __restrict__ out) {
    extern __shared__ char smem[];
    hgemm_body(smem, g_att, w, b, out, C_DIM);
}

// ---------------------------------------------------------------
// Kernel 3: HMMA attention, register softmax, ldmatrix fragments.
// One CTA per (b,h). smem = 89088 B -> 2 CTAs/SM.
// ---------------------------------------------------------------
#define PM    128
#define PRB   272                 // P row pitch (bytes)
#define PREG  (PM * PRB)          // 34816
#define VRB   272
#define VREG  (HD * VRB)          // 8704
#define OFF_VT   (2 * PREG)             // 69632
#define OFF_RED  (OFF_VT + 2 * VREG)    // 87040
#define ATTN_SMEM (OFF_RED + 2048)      // 89088

__global__ void __launch_bounds__(256, 2)
attn_hmma_kernel(const float* __restrict__ mask) {
    extern __shared__ char smem[];
    const int tid  = threadIdx.x;
    const int wid  = tid >> 5;
    const int lane = tid & 31;
    const int g = lane >> 2;
    const int t = lane & 3;
    const int bh = blockIdx.x;
    const int b  = bh >> 3;
    const int h  = bh & 7;
    const float scale = 0.17677669529663687f;   // 1/sqrt(32)

    char*  qk = smem;                    // q hi/lo, k hi/lo (RB=80), phase 1 only
    char*  Pz = smem;                    // P hi/lo (overlays qk after sync)
    char*  vt = smem + OFF_VT;
    float* redM = reinterpret_cast<float*>(smem + OFF_RED);        // [2][128]
    float* redS = redM + 256;                                      // [2][128]
    const uint32_t sb = smem_u32(smem);

    // ---- phase 0: load q,k (split, RB=80 layout) and V^T (split) ----
#pragma unroll
    for (int i = 0; i < 4; i++) {
        int s = tid + 256 * i;          // 1024 slots: 128 rows x 8 quads
        int row = s >> 3;
        int c4  = (s & 7) << 2;
        float4 qv = make_float4(0.f, 0.f, 0.f, 0.f);
        float4 kv = qv;
        if (row < N_TOK) {
            size_t base = ((size_t)(b * N_TOK + row)) * QKV_N + h * HD + c4;
            qv = *reinterpret_cast<const float4*>(g_qkv + base);
            kv = *reinterpret_cast<const float4*>(g_qkv + base + C_DIM);
            qv.x *= scale; qv.y *= scale; qv.z *= scale; qv.w *= scale;
        }
        int off = row * RB + c4 * 2;
        uint32_t h01, l01, h23, l23;
        split2(qv.x, qv.y, h01, l01);
        split2(qv.z, qv.w, h23, l23);
        *reinterpret_cast<uint2*>(qk + off)         = make_uint2(h01, h23);
        *reinterpret_cast<uint2*>(qk + REG_B + off) = make_uint2(l01, l23);
        split2(kv.x, kv.y, h01, l01);
        split2(kv.z, kv.w, h23, l23);
        *reinterpret_cast<uint2*>(qk + 2 * REG_B + off) = make_uint2(h01, h23);
        *reinterpret_cast<uint2*>(qk + 3 * REG_B + off) = make_uint2(l01, l23);
    }
    // V^T: vt[d][token-pair] bf16 hi/lo
#pragma unroll
    for (int i = 0; i < 2; i++) {
        int s  = tid + 256 * i;          // 512 slots: 64 token-pairs x 8 d-quads
        int tp = s >> 3;
        int d4 = (s & 7) << 2;
        int t0 = 2 * tp, t1 = 2 * tp + 1;
        float4 v0 = make_float4(0.f, 0.f, 0.f, 0.f), v1 = v0;
        if (t0 < N_TOK)
            v0 = *reinterpret_cast<const float4*>(
                g_qkv + ((size_t)(b * N_TOK + t0)) * QKV_N + h * HD + 2 * C_DIM + d4);
        if (t1 < N_TOK)
            v1 = *reinterpret_cast<const float4*>(
                g_qkv + ((size_t)(b * N_TOK + t1)) * QKV_N + h * HD + 2 * C_DIM + d4);
        float e0[4] = { v0.x, v0.y, v0.z, v0.w };
        float e1[4] = { v1.x, v1.y, v1.z, v1.w };
#pragma unroll
        for (int d = 0; d < 4; d++) {
            uint32_t hi, lo;
            split2(e0[d], e1[d], hi, lo);
            *reinterpret_cast<uint32_t*>(vt + (d4 + d) * VRB + tp * 4)        = hi;
            *reinterpret_cast<uint32_t*>(vt + VREG + (d4 + d) * VRB + tp * 4) = lo;
        }
    }
    __syncthreads();

    // ---- phase 1: S = q k^T via mma (ldmatrix fragments) ----
    const int wm = (wid >> 1) * 32;
    const int wn = (wid & 1) * 64;
    const int wpair = wid & 1;
    float acc[2][8][4];
#pragma unroll
    for (int mt = 0; mt < 2; mt++)
#pragma unroll
        for (int q = 0; q < 8; q++)
#pragma unroll
            for (int j = 0; j < 4; j++) acc[mt][q][j] = 0.f;
    compute_chunk(sb, wm, wn, lane, acc);

    // ---- phase 2: add bias+mask (float2, pair shares bound); pad = -1e9 ----
    {
        const float* bp = g_bias + (size_t)h * (N_TOK * N_TOK);
        const float* mp = mask + (size_t)(b & (NW - 1)) * (N_TOK * N_TOK);
#pragma unroll
        for (int mt = 0; mt < 2; mt++) {
            int rr0 = wm + mt * 16 + g;
            int rr1 = rr0 + 8;
#pragma unroll
            for (int q = 0; q < 8; q++) {
                int cc = wn + q * 8 + 2 * t;
                if (cc < N_TOK && rr0 < N_TOK) {
                    float2 bb = *reinterpret_cast<const float2*>(bp + rr0 * N_TOK + cc);
                    float2 mm = *reinterpret_cast<const float2*>(mp + rr0 * N_TOK + cc);
                    acc[mt][q][0] += bb.x + mm.x;
                    acc[mt][q][1] += bb.y + mm.y;
                } else {
                    acc[mt][q][0] = -1e9f;
                    acc[mt][q][1] = -1e9f;
                }
                if (cc < N_TOK && rr1 < N_TOK) {
                    float2 bb = *reinterpret_cast<const float2*>(bp + rr1 * N_TOK + cc);
                    float2 mm = *reinterpret_cast<const float2*>(mp + rr1 * N_TOK + cc);
                    acc[mt][q][2] += bb.x + mm.x;
                    acc[mt][q][3] += bb.y + mm.y;
                } else {
                    acc[mt][q][2] = -1e9f;
                    acc[mt][q][3] = -1e9f;
                }
            }
        }
    }

    // ---- phase 3: register softmax ----
#pragma unroll
    for (int mt = 0; mt < 2; mt++) {
        float m0 = -1e30f, m1 = -1e30f;
#pragma unroll
        for (int q = 0; q < 8; q++) {
            m0 = fmaxf(m0, fmaxf(acc[mt][q][0], acc[mt][q][1]));
            m1 = fmaxf(m1, fmaxf(acc[mt][q][2], acc[mt][q][3]));
        }
#pragma unroll
        for (int off = 1; off <= 2; off <<= 1) {
            m0 = fmaxf(m0, __shfl_xor_sync(0xFFFFFFFFu, m0, off));
            m1 = fmaxf(m1, __shfl_xor_sync(0xFFFFFFFFu, m1, off));
        }
        if (t == 0) {
            redM[wpair * PM + wm + mt * 16 + g]     = m0;
            redM[wpair * PM + wm + mt * 16 + g + 8] = m1;
        }
    }
    __syncthreads();

#pragma unroll
    for (int mt = 0; mt < 2; mt++) {
        int r0 = wm + mt * 16 + g;
        float M0 = fmaxf(redM[r0], redM[PM + r0]);
        float M1 = fmaxf(redM[r0 + 8], redM[PM + r0 + 8]);
        float s0 = 0.f, s1 = 0.f;
#pragma unroll
        for (int q = 0; q < 8; q++) {
            float e0 = __expf(acc[mt][q][0] - M0);
            float e1 = __expf(acc[mt][q][1] - M0);
            float e2 = __expf(acc[mt][q][2] - M1);
            float e3 = __expf(acc[mt][q][3] - M1);
            acc[mt][q][0] = e0; acc[mt][q][1] = e1;
            acc[mt][q][2] = e2; acc[mt][q][3] = e3;
            s0 += e0 + e1;
            s1 += e2 + e3;
        }
#pragma unroll
        for (int off = 1; off <= 2; off <<= 1) {
            s0 += __shfl_xor_sync(0xFFFFFFFFu, s0, off);
            s1 += __shfl_xor_sync(0xFFFFFFFFu, s1, off);
        }
        if (t == 0) {
            redS[wpair * PM + r0]     = s0;
            redS[wpair * PM + r0 + 8] = s1;
        }
    }
    __syncthreads();   // also fences qk reads (done) vs Pz writes below

    // normalize + write P split bf16 hi/lo directly into Pz
#pragma unroll
    for (int mt = 0; mt < 2; mt++) {
        int r0 = wm + mt * 16 + g;
        float inv0 = 1.f / (redS[r0] + redS[PM + r0]);
        float inv1 = 1.f / (redS[r0 + 8] + redS[PM + r0 + 8]);
#pragma unroll
        for (int q = 0; q < 8; q++) {
            int cc = wn + q * 8 + 2 * t;
            uint32_t hi, lo;
            split2(acc[mt][q][0] * inv0, acc[mt][q][1] * inv0, hi, lo);
            *reinterpret_cast<uint32_t*>(Pz + r0 * PRB + cc * 2)        = hi;
            *reinterpret_cast<uint32_t*>(Pz + PREG + r0 * PRB + cc * 2) = lo;
            split2(acc[mt][q][2] * inv1, acc[mt][q][3] * inv1, hi, lo);
            *reinterpret_cast<uint32_t*>(Pz + (r0 + 8) * PRB + cc * 2)        = hi;
            *reinterpret_cast<uint32_t*>(Pz + PREG + (r0 + 8) * PRB + cc * 2) = lo;
        }
    }
    __syncthreads();

    // ---- phase 4: O = P V via mma (ldmatrix fragments) ----
    const int wn2 = (wid & 1) * 16;
    const int arow  = lane & 15;
    const int acol2 = ((lane >> 4) << 3) * 2;
    const int brow  = (lane & 7) + ((lane >> 3) & 2) * 4;
    const int bcol2 = (((lane >> 3) & 1) << 3) * 2;
    float oacc[2][2][4];
#pragma unroll
    for (int mt = 0; mt < 2; mt++)
#pragma unroll
        for (int q = 0; q < 2; q++)
#pragma unroll
            for (int j = 0; j < 4; j++) oacc[mt][q][j] = 0.f;

#pragma unroll
    for (int kc = 0; kc < 8; kc++) {
        const int ks = kc * 16;
        uint32_t ah[2][4], al[2][4];
#pragma unroll
        for (int mt = 0; mt < 2; mt++) {
            uint32_t aaddr = sb + (wm + mt * 16 + arow) * PRB + ks * 2 + acol2;
            ldsm4(ah[mt], aaddr);
            ldsm4(al[mt], aaddr + PREG);
        }
        uint32_t baddr = sb + OFF_VT + (wn2 + brow) * VRB + ks * 2 + bcol2;
        uint32_t bh[4], bl[4];
        ldsm4(bh, baddr);
        ldsm4(bl, baddr + VREG);
#pragma unroll
        for (int hf = 0; hf < 2; hf++) {
#pragma unroll
            for (int mt = 0; mt < 2; mt++) {
                mma16816(oacc[mt][hf], ah[mt], bh + 2 * hf);
                mma16816(oacc[mt][hf], ah[mt], bl + 2 * hf);
                mma16816(oacc[mt][hf], al[mt], bh + 2 * hf);
            }
        }
    }

    // ---- phase 5: write O rows < 98 ----
#pragma unroll
    for (int mt = 0; mt < 2; mt++) {
#pragma unroll
        for (int q = 0; q < 2; q++) {
            int rr = wm + mt * 16 + g;
            int cc = h * HD + wn2 + q * 8 + 2 * t;
            if (rr < N_TOK)
                *reinterpret_cast<float2*>(g_att + (size_t)(b * N_TOK + rr) * C_DIM + cc)
                    = make_float2(oacc[mt][q][0], oacc[mt][q][1]);
            if (rr + 8 < N_TOK)
                *reinterpret_cast<float2*>(g_att + (size_t)(b * N_TOK + rr + 8) * C_DIM + cc)
                    = make_float2(oacc[mt][q][2], oacc[mt][q][3]);
        }
    }
}

// ---------------------------------------------------------------
// Launch
// ---------------------------------------------------------------
extern "C" void kernel_launch(void* const* d_in, const int* in_sizes, int n_in,
                              void* d_out, int out_size) {
    const float* x          = (const float*)d_in[0];
    const float* mask       = (const float*)d_in[1];
    const float* qkv_w      = (const float*)d_in[2];
    const float* qkv_b      = (const float*)d_in[3];
    const float* proj_w     = (const float*)d_in[4];
    const float* proj_b     = (const float*)d_in[5];
    const float* bias_table = (const float*)d_in[6];
    const int*   rel_index  = (const int*)d_in[7];
    float* out = (float*)d_out;

    cudaFuncSetAttribute(attn_hmma_kernel,
                         cudaFuncAttributeMaxDynamicSharedMemorySize, ATTN_SMEM);
    const int gemm_smem = 2 * BUF_B;   // 81920
    cudaFuncSetAttribute(qkv_gemm_kernel,
                         cudaFuncAttributeMaxDynamicSharedMemorySize, gemm_smem);
    cudaFuncSetAttribute(proj_gemm_kernel,
                         cudaFuncAttributeMaxDynamicSharedMemorySize, gemm_smem);

    // 1) bias gather
    {
        int total = H_NUM * N_TOK * N_TOK;
        gather_bias_kernel<<<(total + 255) / 256, 256>>>(bias_table, rel_index);
    }
    // 2) QKV projection (HMMA bf16x3): [200704,256] x [768,256]^T -> g_qkv
    {
        dim3 grid(QKV_N / 128, M_ROWS / 128);
        qkv_gemm_kernel<<<grid, 256, gemm_smem>>>(x, qkv_w, qkv_b);
    }
    // 3) HMMA attention per (b,h), register softmax
    {
        attn_hmma_kernel<<<B_TOT * H_NUM, 256, ATTN_SMEM>>>(mask);
    }
    // 4) output projection (HMMA bf16x3): [200704,256] x [256,256]^T -> d_out
    {
        dim3 grid(C_DIM / 128, M_ROWS / 128);
        proj_gemm_kernel<<<grid, 256, gemm_smem>>>(proj_w, proj_b, out);
    }
}

// round 11
// speedup vs baseline: 2.1996x; 1.0362x over previous
#include <cuda_runtime.h>
#include <cuda_bf16.h>
#include <cstdint>

// Problem constants
#define B_TOT   2048
#define N_TOK   98
#define C_DIM   256
#define H_NUM   8
#define HD      32
#define NW      512
#define M_ROWS  (B_TOT * N_TOK)          // 200704
#define QKV_N   (3 * C_DIM)              // 768

// -------- scratch (static device globals: no runtime allocation) --------
// NOTE: referenced ONLY from device code (host-passed shadow addrs read as
// zeros via ATS on GB300 — the silent R3-R6 bug).
__device__ float g_qkv[(size_t)M_ROWS * QKV_N];   // ~616 MB
__device__ float g_att[(size_t)M_ROWS * C_DIM];   // ~205 MB
__device__ float g_bias[H_NUM * N_TOK * N_TOK];

// ================= helpers =================
__device__ __forceinline__ uint32_t smem_u32(const void* p) {
    uint32_t a;
    asm("{ .reg .u64 t; cvta.to.shared.u64 t, %1; cvt.u32.u64 %0, t; }"
        : "=r"(a) : "l"(p));
    return a;
}

__device__ __forceinline__ void mma16816(float* c, const uint32_t* a, const uint32_t* b) {
    asm volatile(
        "mma.sync.aligned.m16n8k16.row.col.f32.bf16.bf16.f32 "
        "{%0,%1,%2,%3}, {%4,%5,%6,%7}, {%8,%9}, {%0,%1,%2,%3};"
        : "+f"(c[0]), "+f"(c[1]), "+f"(c[2]), "+f"(c[3])
        : "r"(a[0]), "r"(a[1]), "r"(a[2]), "r"(a[3]), "r"(b[0]), "r"(b[1]));
}

__device__ __forceinline__ void ldsm4(uint32_t* r, uint32_t addr) {
    asm volatile("ldmatrix.sync.aligned.m8n8.x4.shared.b16 {%0,%1,%2,%3}, [%4];"
                 : "=r"(r[0]), "=r"(r[1]), "=r"(r[2]), "=r"(r[3]) : "r"(addr));
}

__device__ __forceinline__ void split2(float x, float y, uint32_t& hi, uint32_t& lo) {
    __nv_bfloat16 hx = __float2bfloat16(x);
    __nv_bfloat16 hy = __float2bfloat16(y);
    __nv_bfloat16 lx = __float2bfloat16(x - __bfloat162float(hx));
    __nv_bfloat16 ly = __float2bfloat16(y - __bfloat162float(hy));
    hi = (uint32_t)__bfloat16_as_ushort(hx) | ((uint32_t)__bfloat16_as_ushort(hy) << 16);
    lo = (uint32_t)__bfloat16_as_ushort(lx) | ((uint32_t)__bfloat16_as_ushort(ly) << 16);
}

__device__ __forceinline__ uint32_t lds32(const char* p) {
    return *reinterpret_cast<const uint32_t*>(p);
}

// ---------------------------------------------------------------
// Kernel 1: gather relative-position bias  -> g_bias[h][n][m]
// ---------------------------------------------------------------
__global__ void gather_bias_kernel(const float* __restrict__ table,
                                   const int* __restrict__ rel) {
    int idx = blockIdx.x * blockDim.x + threadIdx.x;
    const int total = H_NUM * N_TOK * N_TOK;
    if (idx < total) {
        int h  = idx / (N_TOK * N_TOK);
        int nm = idx % (N_TOK * N_TOK);
        g_bias[idx] = table[rel[nm] * H_NUM + h];
    }
}

// ---------------------------------------------------------------
// HMMA bf16x3 split GEMM, scalar fragment loads, term-major mma order.
// CTA: 128x128 tile, BK=32, 8 warps (4x2) of 32x64.
// ---------------------------------------------------------------
#define RB    80          // row bytes (40 halves)
#define REG_B 10240       // region bytes
#define BUF_B 40960       // buffer bytes

__device__ __forceinline__ void ld_chunk(const float* __restrict__ A,
                                         const float* __restrict__ W,
                                         int m0, int n0, int k0, int tid,
                                         float4* r) {
#pragma unroll
    for (int i = 0; i < 4; i++) {
        int f4  = tid + i * 256;
        int row = f4 >> 3;
        int c4  = (f4 & 7) << 2;
        r[i]     = *reinterpret_cast<const float4*>(A + (size_t)(m0 + row) * C_DIM + k0 + c4);
        r[4 + i] = *reinterpret_cast<const float4*>(W + (size_t)(n0 + row) * C_DIM + k0 + c4);
    }
}

__device__ __forceinline__ void st_chunk(char* buf, int tid, const float4* r) {
#pragma unroll
    for (int i = 0; i < 4; i++) {
        int f4  = tid + i * 256;
        int row = f4 >> 3;
        int c4  = (f4 & 7) << 2;
        int off = row * RB + c4 * 2;
        uint32_t h01, l01, h23, l23;
        split2(r[i].x, r[i].y, h01, l01);
        split2(r[i].z, r[i].w, h23, l23);
        *reinterpret_cast<uint2*>(buf + off)         = make_uint2(h01, h23);
        *reinterpret_cast<uint2*>(buf + REG_B + off) = make_uint2(l01, l23);
        split2(r[4 + i].x, r[4 + i].y, h01, l01);
        split2(r[4 + i].z, r[4 + i].w, h23, l23);
        *reinterpret_cast<uint2*>(buf + 2 * REG_B + off) = make_uint2(h01, h23);
        *reinterpret_cast<uint2*>(buf + 3 * REG_B + off) = make_uint2(l01, l23);
    }
}

// scalar-LDS fragments, term-major issue (8 independent mma between
// accumulator reuses instead of back-to-back dependent triples).
__device__ __forceinline__ void compute_chunk_s(const char* sbuf, int wm, int wn,
                                                int lane, float acc[2][8][4]) {
    const int g = lane >> 2;
    const int t = lane & 3;
#pragma unroll
    for (int ks = 0; ks < 32; ks += 16) {
        uint32_t ah[2][4], al[2][4];
#pragma unroll
        for (int mt = 0; mt < 2; mt++) {
            const char* a0p = sbuf + (wm + mt * 16 + g) * RB + (ks + 2 * t) * 2;
            ah[mt][0] = lds32(a0p);
            ah[mt][1] = lds32(a0p + 8 * RB);
            ah[mt][2] = lds32(a0p + 16);
            ah[mt][3] = lds32(a0p + 8 * RB + 16);
            al[mt][0] = lds32(a0p + REG_B);
            al[mt][1] = lds32(a0p + REG_B + 8 * RB);
            al[mt][2] = lds32(a0p + REG_B + 16);
            al[mt][3] = lds32(a0p + REG_B + 8 * RB + 16);
        }
#pragma unroll
        for (int qh = 0; qh < 2; qh++) {           // groups of 4 q-tiles
            uint32_t bh[4][2], bl[4][2];
#pragma unroll
            for (int q4 = 0; q4 < 4; q4++) {
                const char* b0p = sbuf + 2 * REG_B
                    + (wn + (qh * 4 + q4) * 8 + g) * RB + (ks + 2 * t) * 2;
                bh[q4][0] = lds32(b0p);
                bh[q4][1] = lds32(b0p + 16);
                bl[q4][0] = lds32(b0p + REG_B);
                bl[q4][1] = lds32(b0p + REG_B + 16);
            }
            // term 1: hi*hi  (8 independent)
#pragma unroll
            for (int q4 = 0; q4 < 4; q4++)
#pragma unroll
                for (int mt = 0; mt < 2; mt++)
                    mma16816(acc[mt][qh * 4 + q4], ah[mt], bh[q4]);
            // term 2: hi*lo
#pragma unroll
            for (int q4 = 0; q4 < 4; q4++)
#pragma unroll
                for (int mt = 0; mt < 2; mt++)
                    mma16816(acc[mt][qh * 4 + q4], ah[mt], bl[q4]);
            // term 3: lo*hi
#pragma unroll
            for (int q4 = 0; q4 < 4; q4++)
#pragma unroll
                for (int mt = 0; mt < 2; mt++)
                    mma16816(acc[mt][qh * 4 + q4], al[mt], bh[q4]);
        }
    }
}

__device__ __forceinline__ void hgemm_body(char* smem,
                                           const float* __restrict__ A,
                                           const float* __restrict__ W,
                                           const float* __restrict__ bias,
                                           float* __restrict__ C, int Ntot) {
    const int tid  = threadIdx.x;
    const int wid  = tid >> 5;
    const int lane = tid & 31;
    const int m0 = blockIdx.y * 128;
    const int n0 = blockIdx.x * 128;
    const int wm = (wid >> 1) * 32;
    const int wn = (wid & 1) * 64;

    float acc[2][8][4];
#pragma unroll
    for (int mt = 0; mt < 2; mt++)
#pragma unroll
        for (int nt = 0; nt < 8; nt++)
#pragma unroll
            for (int j = 0; j < 4; j++) acc[mt][nt][j] = 0.f;

    float4 pref[8];
    ld_chunk(A, W, m0, n0, 0, tid, pref);
    st_chunk(smem, tid, pref);
    __syncthreads();

#pragma unroll 1
    for (int ch = 0; ch < 8; ch++) {
        if (ch < 7) ld_chunk(A, W, m0, n0, (ch + 1) * 32, tid, pref);
        compute_chunk_s(smem + (ch & 1) * BUF_B, wm, wn, lane, acc);
        if (ch < 7) st_chunk(smem + ((ch + 1) & 1) * BUF_B, tid, pref);
        __syncthreads();
    }

    const int g = lane >> 2;
    const int t = lane & 3;
#pragma unroll
    for (int mt = 0; mt < 2; mt++) {
#pragma unroll
        for (int q = 0; q < 8; q++) {
            int rr = m0 + wm + mt * 16 + g;
            int cc = n0 + wn + q * 8 + 2 * t;
            float b0 = bias[cc], b1 = bias[cc + 1];
            float2 v0 = make_float2(acc[mt][q][0] + b0, acc[mt][q][1] + b1);
            float2 v1 = make_float2(acc[mt][q][2] + b0, acc[mt][q][3] + b1);
            *reinterpret_cast<float2*>(C + (size_t)rr * Ntot + cc)       = v0;
            *reinterpret_cast<float2*>(C + (size_t)(rr + 8) * Ntot + cc) = v1;
        }
    }
}

__global__ void __launch_bounds__(256, 2)
qkv_gemm_kernel(const float* __restrict__ x, const float* __restrict__ w,
                const float* __restrict__ b) {
    extern __shared__ char smem[];
    hgemm_body(smem, x, w, b, g_qkv, QKV_N);
}

__global__ void __launch_bounds__(256, 2)
proj_gemm_kernel(const float* __restrict__ w, const float* __restrict__ b,
                 float* __restrict__ out) {
    extern __shared__ char smem[];
    hgemm_body(smem, g_att, w, b, out, C_DIM);
}

// ---------------------------------------------------------------
// Kernel 3: HMMA attention (unchanged from R10 — ldmatrix + register
// softmax; proven ~560us). One CTA per (b,h). smem 89088 -> 2 CTAs/SM.
// ---------------------------------------------------------------
#define PM    128
#define PRB   272                 // P row pitch (bytes)
#define PREG  (PM * PRB)          // 34816
#define VRB   272
#define VREG  (HD * VRB)          // 8704
#define OFF_VT   (2 * PREG)             // 69632
#define OFF_RED  (OFF_VT + 2 * VREG)    // 87040
#define ATTN_SMEM (OFF_RED + 2048)      // 89088

// ldmatrix chunk for attention QK^T (RB=80 layout)
__device__ __forceinline__ void compute_chunk_l(uint32_t sbuf, int wm, int wn,
                                                int lane, float acc[2][8][4]) {
    const int arow  = lane & 15;
    const int acol2 = ((lane >> 4) << 3) * 2;
    const int brow  = (lane & 7) + ((lane >> 3) & 2) * 4;
    const int bcol2 = (((lane >> 3) & 1) << 3) * 2;
#pragma unroll
    for (int ks = 0; ks < 32; ks += 16) {
        uint32_t ah[2][4], al[2][4];
#pragma unroll
        for (int mt = 0; mt < 2; mt++) {
            uint32_t aaddr = sbuf + (wm + mt * 16 + arow) * RB + ks * 2 + acol2;
            ldsm4(ah[mt], aaddr);
            ldsm4(al[mt], aaddr + REG_B);
        }
#pragma unroll
        for (int qp = 0; qp < 4; qp++) {
            uint32_t baddr = sbuf + 2 * REG_B + (wn + qp * 16 + brow) * RB + ks * 2 + bcol2;
            uint32_t bh[4], bl[4];
            ldsm4(bh, baddr);
            ldsm4(bl, baddr + REG_B);
            // term-major within the q-pair (4 independent per term)
#pragma unroll
            for (int hf = 0; hf < 2; hf++)
#pragma unroll
                for (int mt = 0; mt < 2; mt++)
                    mma16816(acc[mt][qp * 2 + hf], ah[mt], bh + 2 * hf);
#pragma unroll
            for (int hf = 0; hf < 2; hf++)
#pragma unroll
                for (int mt = 0; mt < 2; mt++)
                    mma16816(acc[mt][qp * 2 + hf], ah[mt], bl + 2 * hf);
#pragma unroll
            for (int hf = 0; hf < 2; hf++)
#pragma unroll
                for (int mt = 0; mt < 2; mt++)
                    mma16816(acc[mt][qp * 2 + hf], al[mt], bh + 2 * hf);
        }
    }
}

__global__ void __launch_bounds__(256, 2)
attn_hmma_kernel(const float* __restrict__ mask) {
    extern __shared__ char smem[];
    const int tid  = threadIdx.x;
    const int wid  = tid >> 5;
    const int lane = tid & 31;
    const int g = lane >> 2;
    const int t = lane & 3;
    const int bh = blockIdx.x;
    const int b  = bh >> 3;
    const int h  = bh & 7;
    const float scale = 0.17677669529663687f;   // 1/sqrt(32)

    char*  qk = smem;                    // q hi/lo, k hi/lo (RB=80), phase 1 only
    char*  Pz = smem;                    // P hi/lo (overlays qk after sync)
    char*  vt = smem + OFF_VT;
    float* redM = reinterpret_cast<float*>(smem + OFF_RED);        // [2][128]
    float* redS = redM + 256;                                      // [2][128]
    const uint32_t sb = smem_u32(smem);

    // ---- phase 0: load q,k (split, RB=80 layout) and V^T (split) ----
#pragma unroll
    for (int i = 0; i < 4; i++) {
        int s = tid + 256 * i;          // 1024 slots: 128 rows x 8 quads
        int row = s >> 3;
        int c4  = (s & 7) << 2;
        float4 qv = make_float4(0.f, 0.f, 0.f, 0.f);
        float4 kv = qv;
        if (row < N_TOK) {
            size_t base = ((size_t)(b * N_TOK + row)) * QKV_N + h * HD + c4;
            qv = *reinterpret_cast<const float4*>(g_qkv + base);
            kv = *reinterpret_cast<const float4*>(g_qkv + base + C_DIM);
            qv.x *= scale; qv.y *= scale; qv.z *= scale; qv.w *= scale;
        }
        int off = row * RB + c4 * 2;
        uint32_t h01, l01, h23, l23;
        split2(qv.x, qv.y, h01, l01);
        split2(qv.z, qv.w, h23, l23);
        *reinterpret_cast<uint2*>(qk + off)         = make_uint2(h01, h23);
        *reinterpret_cast<uint2*>(qk + REG_B + off) = make_uint2(l01, l23);
        split2(kv.x, kv.y, h01, l01);
        split2(kv.z, kv.w, h23, l23);
        *reinterpret_cast<uint2*>(qk + 2 * REG_B + off) = make_uint2(h01, h23);
        *reinterpret_cast<uint2*>(qk + 3 * REG_B + off) = make_uint2(l01, l23);
    }
    // V^T: vt[d][token-pair] bf16 hi/lo
#pragma unroll
    for (int i = 0; i < 2; i++) {
        int s  = tid + 256 * i;          // 512 slots: 64 token-pairs x 8 d-quads
        int tp = s >> 3;
        int d4 = (s & 7) << 2;
        int t0 = 2 * tp, t1 = 2 * tp + 1;
        float4 v0 = make_float4(0.f, 0.f, 0.f, 0.f), v1 = v0;
        if (t0 < N_TOK)
            v0 = *reinterpret_cast<const float4*>(
                g_qkv + ((size_t)(b * N_TOK + t0)) * QKV_N + h * HD + 2 * C_DIM + d4);
        if (t1 < N_TOK)
            v1 = *reinterpret_cast<const float4*>(
                g_qkv + ((size_t)(b * N_TOK + t1)) * QKV_N + h * HD + 2 * C_DIM + d4);
        float e0[4] = { v0.x, v0.y, v0.z, v0.w };
        float e1[4] = { v1.x, v1.y, v1.z, v1.w };
#pragma unroll
        for (int d = 0; d < 4; d++) {
            uint32_t hi, lo;
            split2(e0[d], e1[d], hi, lo);
            *reinterpret_cast<uint32_t*>(vt + (d4 + d) * VRB + tp * 4)        = hi;
            *reinterpret_cast<uint32_t*>(vt + VREG + (d4 + d) * VRB + tp * 4) = lo;
        }
    }
    __syncthreads();

    // ---- phase 1: S = q k^T via mma (ldmatrix fragments) ----
    const int wm = (wid >> 1) * 32;
    const int wn = (wid & 1) * 64;
    const int wpair = wid & 1;
    float acc[2][8][4];
#pragma unroll
    for (int mt = 0; mt < 2; mt++)
#pragma unroll
        for (int q = 0; q < 8; q++)
#pragma unroll
            for (int j = 0; j < 4; j++) acc[mt][q][j] = 0.f;
    compute_chunk_l(sb, wm, wn, lane, acc);

    // ---- phase 2: add bias+mask (float2); pad = -1e9 ----
    {
        const float* bp = g_bias + (size_t)h * (N_TOK * N_TOK);
        const float* mp = mask + (size_t)(b & (NW - 1)) * (N_TOK * N_TOK);
#pragma unroll
        for (int mt = 0; mt < 2; mt++) {
            int rr0 = wm + mt * 16 + g;
            int rr1 = rr0 + 8;
#pragma unroll
            for (int q = 0; q < 8; q++) {
                int cc = wn + q * 8 + 2 * t;
                if (cc < N_TOK && rr0 < N_TOK) {
                    float2 bb = *reinterpret_cast<const float2*>(bp + rr0 * N_TOK + cc);
                    float2 mm = *reinterpret_cast<const float2*>(mp + rr0 * N_TOK + cc);
                    acc[mt][q][0] += bb.x + mm.x;
                    acc[mt][q][1] += bb.y + mm.y;
                } else {
                    acc[mt][q][0] = -1e9f;
                    acc[mt][q][1] = -1e9f;
                }
                if (cc < N_TOK && rr1 < N_TOK) {
                    float2 bb = *reinterpret_cast<const float2*>(bp + rr1 * N_TOK + cc);
                    float2 mm = *reinterpret_cast<const float2*>(mp + rr1 * N_TOK + cc);
                    acc[mt][q][2] += bb.x + mm.x;
                    acc[mt][q][3] += bb.y + mm.y;
                } else {
                    acc[mt][q][2] = -1e9f;
                    acc[mt][q][3] = -1e9f;
                }
            }
        }
    }

    // ---- phase 3: register softmax ----
#pragma unroll
    for (int mt = 0; mt < 2; mt++) {
        float m0 = -1e30f, m1 = -1e30f;
#pragma unroll
        for (int q = 0; q < 8; q++) {
            m0 = fmaxf(m0, fmaxf(acc[mt][q][0], acc[mt][q][1]));
            m1 = fmaxf(m1, fmaxf(acc[mt][q][2], acc[mt][q][3]));
        }
#pragma unroll
        for (int off = 1; off <= 2; off <<= 1) {
            m0 = fmaxf(m0, __shfl_xor_sync(0xFFFFFFFFu, m0, off));
            m1 = fmaxf(m1, __shfl_xor_sync(0xFFFFFFFFu, m1, off));
        }
        if (t == 0) {
            redM[wpair * PM + wm + mt * 16 + g]     = m0;
            redM[wpair * PM + wm + mt * 16 + g + 8] = m1;
        }
    }
    __syncthreads();

#pragma unroll
    for (int mt = 0; mt < 2; mt++) {
        int r0 = wm + mt * 16 + g;
        float M0 = fmaxf(redM[r0], redM[PM + r0]);
        float M1 = fmaxf(redM[r0 + 8], redM[PM + r0 + 8]);
        float s0 = 0.f, s1 = 0.f;
#pragma unroll
        for (int q = 0; q < 8; q++) {
            float e0 = __expf(acc[mt][q][0] - M0);
            float e1 = __expf(acc[mt][q][1] - M0);
            float e2 = __expf(acc[mt][q][2] - M1);
            float e3 = __expf(acc[mt][q][3] - M1);
            acc[mt][q][0] = e0; acc[mt][q][1] = e1;
            acc[mt][q][2] = e2; acc[mt][q][3] = e3;
            s0 += e0 + e1;
            s1 += e2 + e3;
        }
#pragma unroll
        for (int off = 1; off <= 2; off <<= 1) {
            s0 += __shfl_xor_sync(0xFFFFFFFFu, s0, off);
            s1 += __shfl_xor_sync(0xFFFFFFFFu, s1, off);
        }
        if (t == 0) {
            redS[wpair * PM + r0]     = s0;
            redS[wpair * PM + r0 + 8] = s1;
        }
    }
    __syncthreads();   // also fences qk reads (done) vs Pz writes below

    // normalize + write P split bf16 hi/lo directly into Pz
#pragma unroll
    for (int mt = 0; mt < 2; mt++) {
        int r0 = wm + mt * 16 + g;
        float inv0 = 1.f / (redS[r0] + redS[PM + r0]);
        float inv1 = 1.f / (redS[r0 + 8] + redS[PM + r0 + 8]);
#pragma unroll
        for (int q = 0; q < 8; q++) {
            int cc = wn + q * 8 + 2 * t;
            uint32_t hi, lo;
            split2(acc[mt][q][0] * inv0, acc[mt][q][1] * inv0, hi, lo);
            *reinterpret_cast<uint32_t*>(Pz + r0 * PRB + cc * 2)        = hi;
            *reinterpret_cast<uint32_t*>(Pz + PREG + r0 * PRB + cc * 2) = lo;
            split2(acc[mt][q][2] * inv1, acc[mt][q][3] * inv1, hi, lo);
            *reinterpret_cast<uint32_t*>(Pz + (r0 + 8) * PRB + cc * 2)        = hi;
            *reinterpret_cast<uint32_t*>(Pz + PREG + (r0 + 8) * PRB + cc * 2) = lo;
        }
    }
    __syncthreads();

    // ---- phase 4: O = P V via mma (ldmatrix fragments) ----
    const int wn2 = (wid & 1) * 16;
    const int arow  = lane & 15;
    const int acol2 = ((lane >> 4) << 3) * 2;
    const int brow  = (lane & 7) + ((lane >> 3) & 2) * 4;
    const int bcol2 = (((lane >> 3) & 1) << 3) * 2;
    float oacc[2][2][4];
#pragma unroll
    for (int mt = 0; mt < 2; mt++)
#pragma unroll
        for (int q = 0; q < 2; q++)
#pragma unroll
            for (int j = 0; j < 4; j++) oacc[mt][q][j] = 0.f;

#pragma unroll
    for (int kc = 0; kc < 8; kc++) {
        const int ks = kc * 16;
        uint32_t ah[2][4], al[2][4];
#pragma unroll
        for (int mt = 0; mt < 2; mt++) {
            uint32_t aaddr = sb + (wm + mt * 16 + arow) * PRB + ks * 2 + acol2;
            ldsm4(ah[mt], aaddr);
            ldsm4(al[mt], aaddr + PREG);
        }
        uint32_t baddr = sb + OFF_VT + (wn2 + brow) * VRB + ks * 2 + bcol2;
        uint32_t bh[4], bl[4];
        ldsm4(bh, baddr);
        ldsm4(bl, baddr + VREG);
#pragma unroll
        for (int hf = 0; hf < 2; hf++)
#pragma unroll
            for (int mt = 0; mt < 2; mt++)
                mma16816(oacc[mt][hf], ah[mt], bh + 2 * hf);
#pragma unroll
        for (int hf = 0; hf < 2; hf++)
#pragma unroll
            for (int mt = 0; mt < 2; mt++)
                mma16816(oacc[mt][hf], ah[mt], bl + 2 * hf);
#pragma unroll
        for (int hf = 0; hf < 2; hf++)
#pragma unroll
            for (int mt = 0; mt < 2; mt++)
                mma16816(oacc[mt][hf], al[mt], bh + 2 * hf);
    }

    // ---- phase 5: write O rows < 98 ----
#pragma unroll
    for (int mt = 0; mt < 2; mt++) {
#pragma unroll
        for (int q = 0; q < 2; q++) {
            int rr = wm + mt * 16 + g;
            int cc = h * HD + wn2 + q * 8 + 2 * t;
            if (rr < N_TOK)
                *reinterpret_cast<float2*>(g_att + (size_t)(b * N_TOK + rr) * C_DIM + cc)
                    = make_float2(oacc[mt][q][0], oacc[mt][q][1]);
            if (rr + 8 < N_TOK)
                *reinterpret_cast<float2*>(g_att + (size_t)(b * N_TOK + rr + 8) * C_DIM + cc)
                    = make_float2(oacc[mt][q][2], oacc[mt][q][3]);
        }
    }
}

// ---------------------------------------------------------------
// Launch
// ---------------------------------------------------------------
extern "C" void kernel_launch(void* const* d_in, const int* in_sizes, int n_in,
                              void* d_out, int out_size) {
    const float* x          = (const float*)d_in[0];
    const float* mask       = (const float*)d_in[1];
    const float* qkv_w      = (const float*)d_in[2];
    const float* qkv_b      = (const float*)d_in[3];
    const float* proj_w     = (const float*)d_in[4];
    const float* proj_b     = (const float*)d_in[5];
    const float* bias_table = (const float*)d_in[6];
    const int*   rel_index  = (const int*)d_in[7];
    float* out = (float*)d_out;

    cudaFuncSetAttribute(attn_hmma_kernel,
                         cudaFuncAttributeMaxDynamicSharedMemorySize, ATTN_SMEM);
    const int gemm_smem = 2 * BUF_B;   // 81920
    cudaFuncSetAttribute(qkv_gemm_kernel,
                         cudaFuncAttributeMaxDynamicSharedMemorySize, gemm_smem);
    cudaFuncSetAttribute(proj_gemm_kernel,
                         cudaFuncAttributeMaxDynamicSharedMemorySize, gemm_smem);

    // 1) bias gather
    {
        int total = H_NUM * N_TOK * N_TOK;
        gather_bias_kernel<<<(total + 255) / 256, 256>>>(bias_table, rel_index);
    }
    // 2) QKV projection (HMMA bf16x3): [200704,256] x [768,256]^T -> g_qkv
    {
        dim3 grid(QKV_N / 128, M_ROWS / 128);
        qkv_gemm_kernel<<<grid, 256, gemm_smem>>>(x, qkv_w, qkv_b);
    }
    // 3) HMMA attention per (b,h), register softmax
    {
        attn_hmma_kernel<<<B_TOT * H_NUM, 256, ATTN_SMEM>>>(mask);
    }
    // 4) output projection (HMMA bf16x3): [200704,256] x [256,256]^T -> d_out
    {
        dim3 grid(C_DIM / 128, M_ROWS / 128);
        proj_gemm_kernel<<<grid, 256, gemm_smem>>>(proj_w, proj_b, out);
    }
}